// round 12
// baseline (speedup 1.0000x reference)
#include <cuda_runtime.h>
#include <cuda_fp16.h>
#include <math.h>

#define NNODES 50000
#define NEDGES 800000

// ---------------- scratch (static device globals; no allocation) ----------------
__device__ __align__(16) float g_x  [NNODES * 128];
__device__ __align__(16) float g_t1 [NNODES * 128];
__device__ __align__(16) float g_p  [NNODES * 128];
__device__ __align__(16) float g_h1 [NNODES * 128];
__device__ __align__(16) float g_tmp[NNODES * 128];
__device__ float g_dinv[NNODES];
__device__ int   g_deg [NNODES];
__device__ int   g_cnt [NNODES];
__device__ int   g_rs  [NNODES];
__device__ int   g_rf  [NNODES];
__device__ int   g_bsum[256];
__device__ int   g_boff[256];
__device__ __align__(8) int2 g_epack[NEDGES];   // (src, weight-bits) per CSR slot

// ---------------- CSR build (r6/r11 proven) ----------------
__global__ void count_kernel(const int* __restrict__ src, const int* __restrict__ dst,
                             int* __restrict__ deg, int* __restrict__ cnt, int E) {
    int e = blockIdx.x * blockDim.x + threadIdx.x;
    if (e < E) {
        atomicAdd(&deg[src[e]], 1);
        atomicAdd(&cnt[dst[e]], 1);
    }
}

__global__ void dinv_kernel(const int* __restrict__ deg, float* __restrict__ dinv, int n) {
    int i = blockIdx.x * blockDim.x + threadIdx.x;
    if (i < n) {
        int d = deg[i];
        dinv[i] = (d > 0) ? rsqrtf((float)d) : 0.f;
    }
}

__device__ __forceinline__ int block_incl_scan(int v, int* wsum) {
    int lane = threadIdx.x & 31, wid = threadIdx.x >> 5;
    int x = v;
#pragma unroll
    for (int o = 1; o < 32; o <<= 1) {
        int y = __shfl_up_sync(0xffffffffu, x, o);
        if (lane >= o) x += y;
    }
    if (lane == 31) wsum[wid] = x;
    __syncthreads();
    if (wid == 0) {
        int s = (lane < 8) ? wsum[lane] : 0;
#pragma unroll
        for (int o = 1; o < 8; o <<= 1) {
            int y = __shfl_up_sync(0xffffffffu, s, o);
            if (lane >= o) s += y;
        }
        if (lane < 8) wsum[lane] = s;
    }
    __syncthreads();
    int off = (wid > 0) ? wsum[wid - 1] : 0;
    return x + off;
}

__global__ void scan_block_sum(const int* __restrict__ cnt, int* __restrict__ bsum, int n) {
    __shared__ int wsum[8];
    int i = blockIdx.x * 256 + threadIdx.x;
    int v = (i < n) ? cnt[i] : 0;
    int lane = threadIdx.x & 31, wid = threadIdx.x >> 5;
#pragma unroll
    for (int o = 16; o > 0; o >>= 1) v += __shfl_down_sync(0xffffffffu, v, o);
    if (lane == 0) wsum[wid] = v;
    __syncthreads();
    if (threadIdx.x == 0) {
        int s = 0;
#pragma unroll
        for (int k = 0; k < 8; k++) s += wsum[k];
        bsum[blockIdx.x] = s;
    }
}

__global__ void scan_top(const int* __restrict__ bsum, int* __restrict__ boff, int nb) {
    __shared__ int wsum[8];
    int t = threadIdx.x;
    int v = (t < nb) ? bsum[t] : 0;
    int incl = block_incl_scan(v, wsum);
    if (t < nb) boff[t] = incl - v;
}

__global__ void scan_final(const int* __restrict__ cnt, const int* __restrict__ boff,
                           int* __restrict__ rs, int* __restrict__ rf, int n) {
    __shared__ int wsum[8];
    int i = blockIdx.x * 256 + threadIdx.x;
    int v = (i < n) ? cnt[i] : 0;
    int incl = block_incl_scan(v, wsum);
    int excl = incl - v + boff[blockIdx.x];
    if (i < n) { rs[i] = excl; rf[i] = excl; }
}

__global__ void fill_kernel(const int* __restrict__ src, const int* __restrict__ dst,
                            const float* __restrict__ dinv,
                            int* __restrict__ rf, int2* __restrict__ ep, int E) {
    int e = blockIdx.x * blockDim.x + threadIdx.x;
    if (e < E) {
        int s = src[e], d = dst[e];
        int pos = atomicAdd(&rf[d], 1);
        float w = -dinv[s] * dinv[d];
        ep[pos] = make_int2(s, __float_as_int(w));
    }
}

// ---------------- feature assembly (float4, r6 proven) ----------------
__global__ void build_x_kernel(const int* __restrict__ node_attr,
                               const float4* __restrict__ vis,
                               const float4* __restrict__ emb_len,
                               const float4* __restrict__ emb_id,
                               const float4* __restrict__ emb_lng,
                               const float4* __restrict__ emb_lat,
                               float4* __restrict__ x, int n) {
    int idx = blockIdx.x * blockDim.x + threadIdx.x;
    if (idx >= n * 32) return;
    int node = idx >> 5;
    int q = idx & 31;
    float4 v;
    if (q < 16) {
        int which = q >> 2;
        int sub = q & 3;
        int a;
        const float4* tab;
        if (which == 0)      { a = node_attr[node * 4 + 1]; tab = emb_id; }
        else if (which == 1) { a = node_attr[node * 4 + 0]; tab = emb_len; }
        else if (which == 2) { a = node_attr[node * 4 + 2]; tab = emb_lng; }
        else                 { a = node_attr[node * 4 + 3]; tab = emb_lat; }
        v = tab[a * 4 + sub];
    } else {
        v = vis[node * 16 + (q - 16)];
    }
    x[idx] = v;
}

// ---------------- gather propagation (pipelined metadata prefetch) ----------------
__global__ void prop_gather(const float* __restrict__ t,
                            const int* __restrict__ rs, const int* __restrict__ cnt,
                            const int2* __restrict__ ep,
                            float* __restrict__ out, int n) {
    int warp = (blockIdx.x * blockDim.x + threadIdx.x) >> 5;
    int lane = threadIdx.x & 31;
    if (warp >= n) return;
    int start = rs[warp];
    int end = start + cnt[warp];
    float ax = 0.f, ay = 0.f, az = 0.f, aw = 0.f;
    int j = start;
    if (j + 4 <= end) {
        int2 c0 = ep[j], c1 = ep[j + 1], c2 = ep[j + 2], c3 = ep[j + 3];
        for (; j + 8 <= end; j += 4) {
            int2 n0 = ep[j + 4], n1 = ep[j + 5], n2 = ep[j + 6], n3 = ep[j + 7];
            float4 v0 = *(const float4*)(t + (size_t)c0.x * 128 + lane * 4);
            float4 v1 = *(const float4*)(t + (size_t)c1.x * 128 + lane * 4);
            float4 v2 = *(const float4*)(t + (size_t)c2.x * 128 + lane * 4);
            float4 v3 = *(const float4*)(t + (size_t)c3.x * 128 + lane * 4);
            float w0 = __int_as_float(c0.y), w1 = __int_as_float(c1.y);
            float w2 = __int_as_float(c2.y), w3 = __int_as_float(c3.y);
            ax += w0 * v0.x; ay += w0 * v0.y; az += w0 * v0.z; aw += w0 * v0.w;
            ax += w1 * v1.x; ay += w1 * v1.y; az += w1 * v1.z; aw += w1 * v1.w;
            ax += w2 * v2.x; ay += w2 * v2.y; az += w2 * v2.z; aw += w2 * v2.w;
            ax += w3 * v3.x; ay += w3 * v3.y; az += w3 * v3.z; aw += w3 * v3.w;
            c0 = n0; c1 = n1; c2 = n2; c3 = n3;
        }
        {   // last full chunk (c holds valid metadata)
            float4 v0 = *(const float4*)(t + (size_t)c0.x * 128 + lane * 4);
            float4 v1 = *(const float4*)(t + (size_t)c1.x * 128 + lane * 4);
            float4 v2 = *(const float4*)(t + (size_t)c2.x * 128 + lane * 4);
            float4 v3 = *(const float4*)(t + (size_t)c3.x * 128 + lane * 4);
            float w0 = __int_as_float(c0.y), w1 = __int_as_float(c1.y);
            float w2 = __int_as_float(c2.y), w3 = __int_as_float(c3.y);
            ax += w0 * v0.x; ay += w0 * v0.y; az += w0 * v0.z; aw += w0 * v0.w;
            ax += w1 * v1.x; ay += w1 * v1.y; az += w1 * v1.z; aw += w1 * v1.w;
            ax += w2 * v2.x; ay += w2 * v2.y; az += w2 * v2.z; aw += w2 * v2.w;
            ax += w3 * v3.x; ay += w3 * v3.y; az += w3 * v3.z; aw += w3 * v3.w;
            j += 4;
        }
    }
    for (; j < end; j++) {
        int2 m = ep[j];
        float w = __int_as_float(m.y);
        float4 v = *(const float4*)(t + (size_t)m.x * 128 + lane * 4);
        ax += w * v.x; ay += w * v.y; az += w * v.z; aw += w * v.w;
    }
    *(float4*)(out + (size_t)warp * 128 + lane * 4) = make_float4(ax, ay, az, aw);
}

// ---------------- 3xFP16 (Markidis) GEMM — 512 threads, 32x32 warp tiles ----------------
__device__ __forceinline__ void split_h(float f, __half& hi, __half& lo) {
    hi = __float2half_rn(f);
    lo = __float2half_rn(f - __half2float(hi));
}

__device__ __forceinline__ void mma_f16(float& d0, float& d1, float& d2, float& d3,
                                        unsigned a0, unsigned a1, unsigned a2, unsigned a3,
                                        unsigned b0, unsigned b1) {
    asm volatile(
        "mma.sync.aligned.m16n8k16.row.col.f32.f16.f16.f32 "
        "{%0,%1,%2,%3}, {%4,%5,%6,%7}, {%8,%9}, {%0,%1,%2,%3};"
        : "+f"(d0), "+f"(d1), "+f"(d2), "+f"(d3)
        : "r"(a0), "r"(a1), "r"(a2), "r"(a3), "r"(b0), "r"(b1));
}

// C[M,NOUT] = A[M,KTOT] @ W[KTOT,NOUT] + bias; EPI: 0=none 1=relu 2=elu
// CHEB: A cols 0..127 = A0, 128..255 = A1, 256..383 = 2*A2 - A0
// 512 threads: 16 warps, wm = w&3 (32-row strip), wn = w>>2 (BN/4-wide strip)
template<int KTOT, int NOUT, int EPI, bool CHEB>
__global__ void __launch_bounds__(512)
gemm_f16x2(const float* __restrict__ A0, const float* __restrict__ A1,
           const float* __restrict__ A2, const float* __restrict__ W,
           const float* __restrict__ bias, float* __restrict__ C, int M) {
    constexpr int BM = 128, BK = 32, BN = NOUT;
    constexpr int KP = BK / 2;
    constexpr int WARP_N = BN / 4;
    constexpr int NT = WARP_N / 8;
    constexpr int ASTR = BM + 8;
    constexpr int BSTR = BN + 8;

    __shared__ __half2 Ah[KP][ASTR], Al[KP][ASTR];
    __shared__ __half2 Bh[KP][BSTR], Bl[KP][BSTR];

    const int tid = threadIdx.x;
    const int w = tid >> 5, lane = tid & 31;
    const int wm = w & 3, wn = w >> 2;
    const int gid = lane >> 2, tig = lane & 3;
    const int row0 = blockIdx.x * BM;

    float acc[2][NT][4];
#pragma unroll
    for (int mt = 0; mt < 2; mt++)
#pragma unroll
        for (int nt = 0; nt < NT; nt++)
#pragma unroll
            for (int q = 0; q < 4; q++) acc[mt][nt][q] = 0.f;

    for (int k0 = 0; k0 < KTOT; k0 += BK) {
        // ---- stage A: 1024 float4 slots over 512 threads ----
#pragma unroll
        for (int it = 0; it < 2; it++) {
            int i = tid + it * 512;
            int r = i & 127;
            int c4 = i >> 7;
            int grow = row0 + r;
            int gk = k0 + c4 * 4;
            float4 v = make_float4(0.f, 0.f, 0.f, 0.f);
            if (grow < M) {
                if (CHEB) {
                    if (gk < 128) {
                        v = *(const float4*)(A0 + (size_t)grow * 128 + gk);
                    } else if (gk < 256) {
                        v = *(const float4*)(A1 + (size_t)grow * 128 + (gk - 128));
                    } else {
                        float4 p = *(const float4*)(A2 + (size_t)grow * 128 + (gk - 256));
                        float4 t = *(const float4*)(A0 + (size_t)grow * 128 + (gk - 256));
                        v = make_float4(2.f * p.x - t.x, 2.f * p.y - t.y,
                                        2.f * p.z - t.z, 2.f * p.w - t.w);
                    }
                } else {
                    v = *(const float4*)(A0 + (size_t)grow * KTOT + gk);
                }
            }
            __half hx, lx, hy, ly, hz, lz, hw, lw;
            split_h(v.x, hx, lx); split_h(v.y, hy, ly);
            split_h(v.z, hz, lz); split_h(v.w, hw, lw);
            Ah[c4 * 2 + 0][r] = __halves2half2(hx, hy);
            Ah[c4 * 2 + 1][r] = __halves2half2(hz, hw);
            Al[c4 * 2 + 0][r] = __halves2half2(lx, ly);
            Al[c4 * 2 + 1][r] = __halves2half2(lz, lw);
        }
        // ---- stage B ----
        constexpr int BSLOTS = KP * (BN / 4);
#pragma unroll
        for (int it = 0; it < (BSLOTS + 511) / 512; it++) {
            int i = tid + it * 512;
            if (BSLOTS % 512 != 0 && i >= BSLOTS) break;
            int kp = i / (BN / 4);
            int c = (i % (BN / 4)) * 4;
            float4 v0 = *(const float4*)(W + (size_t)(k0 + 2 * kp + 0) * BN + c);
            float4 v1 = *(const float4*)(W + (size_t)(k0 + 2 * kp + 1) * BN + c);
            float e0[4] = {v0.x, v0.y, v0.z, v0.w};
            float e1[4] = {v1.x, v1.y, v1.z, v1.w};
            __half2 hh[4], ll[4];
#pragma unroll
            for (int jq = 0; jq < 4; jq++) {
                __half h0, l0, h1, l1;
                split_h(e0[jq], h0, l0);
                split_h(e1[jq], h1, l1);
                hh[jq] = __halves2half2(h0, h1);
                ll[jq] = __halves2half2(l0, l1);
            }
            *(uint4*)&Bh[kp][c] = *(const uint4*)hh;
            *(uint4*)&Bl[kp][c] = *(const uint4*)ll;
        }
        __syncthreads();

#pragma unroll
        for (int ks = 0; ks < 2; ks++) {
            const int kb = ks * 8 + tig;
            unsigned ah[2][4], al[2][4];
#pragma unroll
            for (int mt = 0; mt < 2; mt++) {
                int m0 = wm * 32 + mt * 16 + gid;
                ah[mt][0] = *(const unsigned*)&Ah[kb][m0];
                ah[mt][1] = *(const unsigned*)&Ah[kb][m0 + 8];
                ah[mt][2] = *(const unsigned*)&Ah[kb + 4][m0];
                ah[mt][3] = *(const unsigned*)&Ah[kb + 4][m0 + 8];
                al[mt][0] = *(const unsigned*)&Al[kb][m0];
                al[mt][1] = *(const unsigned*)&Al[kb][m0 + 8];
                al[mt][2] = *(const unsigned*)&Al[kb + 4][m0];
                al[mt][3] = *(const unsigned*)&Al[kb + 4][m0 + 8];
            }
            unsigned bh[NT][2], bl[NT][2];
#pragma unroll
            for (int nt = 0; nt < NT; nt++) {
                int n0 = wn * WARP_N + nt * 8 + gid;
                bh[nt][0] = *(const unsigned*)&Bh[kb][n0];
                bh[nt][1] = *(const unsigned*)&Bh[kb + 4][n0];
                bl[nt][0] = *(const unsigned*)&Bl[kb][n0];
                bl[nt][1] = *(const unsigned*)&Bl[kb + 4][n0];
            }
#pragma unroll
            for (int mt = 0; mt < 2; mt++)
#pragma unroll
                for (int nt = 0; nt < NT; nt++) {
                    float* d = acc[mt][nt];
                    mma_f16(d[0], d[1], d[2], d[3],
                            ah[mt][0], ah[mt][1], ah[mt][2], ah[mt][3],
                            bh[nt][0], bh[nt][1]);
                    mma_f16(d[0], d[1], d[2], d[3],
                            ah[mt][0], ah[mt][1], ah[mt][2], ah[mt][3],
                            bl[nt][0], bl[nt][1]);
                    mma_f16(d[0], d[1], d[2], d[3],
                            al[mt][0], al[mt][1], al[mt][2], al[mt][3],
                            bh[nt][0], bh[nt][1]);
                }
        }
        __syncthreads();
    }

#pragma unroll
    for (int mt = 0; mt < 2; mt++) {
#pragma unroll
        for (int nt = 0; nt < NT; nt++) {
            int c0 = wn * WARP_N + nt * 8 + tig * 2;
            float bv0 = bias[c0], bv1 = bias[c0 + 1];
#pragma unroll
            for (int half = 0; half < 2; half++) {
                int r = row0 + wm * 32 + mt * 16 + gid + half * 8;
                if (r >= M) continue;
                float v0 = acc[mt][nt][half * 2 + 0] + bv0;
                float v1 = acc[mt][nt][half * 2 + 1] + bv1;
                if (EPI == 1) { v0 = fmaxf(v0, 0.f); v1 = fmaxf(v1, 0.f); }
                else if (EPI == 2) {
                    v0 = (v0 > 0.f) ? v0 : expm1f(v0);
                    v1 = (v1 > 0.f) ? v1 : expm1f(v1);
                }
                *(float2*)(C + (size_t)r * NOUT + c0) = make_float2(v0, v1);
            }
        }
    }
}

// ---------------- launch ----------------
extern "C" void kernel_launch(void* const* d_in, const int* in_sizes, int n_in,
                              void* d_out, int out_size) {
    const int* edge_index = (const int*)d_in[0];
    const int* node_attr = (const int*)d_in[1];
    const float* vis     = (const float*)d_in[2];
    const float* emb_len = (const float*)d_in[3];
    const float* emb_id  = (const float*)d_in[4];
    const float* emb_lng = (const float*)d_in[5];
    const float* emb_lat = (const float*)d_in[6];
    const float* W0  = (const float*)d_in[7];
    const float* b0  = (const float*)d_in[8];
    const float* W1  = (const float*)d_in[9];
    const float* b1  = (const float*)d_in[10];
    const float* P1  = (const float*)d_in[11];
    const float* pb1 = (const float*)d_in[12];
    const float* P2  = (const float*)d_in[13];
    const float* pb2 = (const float*)d_in[14];

    const int E = in_sizes[0] / 2;
    const int N = in_sizes[1] / 4;
    const int* src = edge_index;
    const int* dst = edge_index + E;

    float *x, *t1, *p, *h1, *tmp, *dinv;
    int *deg, *cnt, *rs, *rf, *bsum, *boff;
    int2* ep;
    cudaGetSymbolAddress((void**)&x,    g_x);
    cudaGetSymbolAddress((void**)&t1,   g_t1);
    cudaGetSymbolAddress((void**)&p,    g_p);
    cudaGetSymbolAddress((void**)&h1,   g_h1);
    cudaGetSymbolAddress((void**)&tmp,  g_tmp);
    cudaGetSymbolAddress((void**)&dinv, g_dinv);
    cudaGetSymbolAddress((void**)&deg,  g_deg);
    cudaGetSymbolAddress((void**)&cnt,  g_cnt);
    cudaGetSymbolAddress((void**)&rs,   g_rs);
    cudaGetSymbolAddress((void**)&rf,   g_rf);
    cudaGetSymbolAddress((void**)&bsum, g_bsum);
    cudaGetSymbolAddress((void**)&boff, g_boff);
    cudaGetSymbolAddress((void**)&ep,   g_epack);

    float* hout = (float*)d_out;
    float* zout = hout + (size_t)N * 128;

    const int nb = (N + 255) / 256;
    const int eb = (E + 255) / 256;
    const int gemm_blocks = (N + 127) / 128;
    const int prop_blocks = (N * 32 + 255) / 256;

    // CSR build + dinv (r6 structure)
    cudaMemsetAsync(deg, 0, N * sizeof(int));
    cudaMemsetAsync(cnt, 0, N * sizeof(int));
    count_kernel<<<eb, 256>>>(src, dst, deg, cnt, E);
    dinv_kernel<<<nb, 256>>>(deg, dinv, N);
    scan_block_sum<<<nb, 256>>>(cnt, bsum, N);
    scan_top<<<1, 256>>>(bsum, boff, nb);
    scan_final<<<nb, 256>>>(cnt, boff, rs, rf, N);
    fill_kernel<<<eb, 256>>>(src, dst, dinv, rf, ep, E);

    // feature assembly
    build_x_kernel<<<(N * 32 + 255) / 256, 256>>>(node_attr, (const float4*)vis,
        (const float4*)emb_len, (const float4*)emb_id,
        (const float4*)emb_lng, (const float4*)emb_lat, (float4*)x, N);

    // ---- conv1 ----
    prop_gather<<<prop_blocks, 256>>>(x, rs, cnt, ep, t1, N);
    prop_gather<<<prop_blocks, 256>>>(t1, rs, cnt, ep, p, N);
    gemm_f16x2<384, 128, 1, true><<<gemm_blocks, 512>>>(x, t1, p, W0, b0, h1, N);

    // ---- conv2 ----
    prop_gather<<<prop_blocks, 256>>>(h1, rs, cnt, ep, t1, N);
    prop_gather<<<prop_blocks, 256>>>(t1, rs, cnt, ep, p, N);
    gemm_f16x2<384, 128, 1, true><<<gemm_blocks, 512>>>(h1, t1, p, W1, b1, hout, N);

    // ---- projection head ----
    gemm_f16x2<128, 128, 2, false><<<gemm_blocks, 512>>>(hout, nullptr, nullptr, P1, pb1, tmp, N);
    gemm_f16x2<128, 64, 0, false><<<gemm_blocks, 512>>>(tmp, nullptr, nullptr, P2, pb2, zout, N);
}

// round 13
// speedup vs baseline: 1.0476x; 1.0476x over previous
#include <cuda_runtime.h>
#include <cuda_fp16.h>
#include <math.h>

#define NNODES 50000
#define NEDGES 800000

// ---------------- scratch (static device globals; no allocation) ----------------
__device__ __align__(16) float g_x  [NNODES * 128];
__device__ __align__(16) float g_t1 [NNODES * 128];
__device__ __align__(16) float g_p  [NNODES * 128];
__device__ __align__(16) float g_h1 [NNODES * 128];
__device__ __align__(16) float g_tmp[NNODES * 128];
__device__ float g_dinv[NNODES];
__device__ int   g_deg [NNODES];
__device__ int   g_cnt [NNODES];
__device__ int   g_rs  [NNODES];
__device__ int   g_rf  [NNODES];
__device__ int   g_bsum[256];
__device__ int   g_boff[256];
__device__ int   g_esrc[NEDGES];
__device__ float g_ew  [NEDGES];

// ---------------- CSR build (round-6 proven) ----------------
__global__ void count_kernel(const int* __restrict__ src, const int* __restrict__ dst,
                             int* __restrict__ deg, int* __restrict__ cnt, int E) {
    int e = blockIdx.x * blockDim.x + threadIdx.x;
    if (e < E) {
        atomicAdd(&deg[src[e]], 1);
        atomicAdd(&cnt[dst[e]], 1);
    }
}

__global__ void dinv_kernel(const int* __restrict__ deg, float* __restrict__ dinv, int n) {
    int i = blockIdx.x * blockDim.x + threadIdx.x;
    if (i < n) {
        int d = deg[i];
        dinv[i] = (d > 0) ? rsqrtf((float)d) : 0.f;
    }
}

__device__ __forceinline__ int block_incl_scan(int v, int* wsum) {
    int lane = threadIdx.x & 31, wid = threadIdx.x >> 5;
    int x = v;
#pragma unroll
    for (int o = 1; o < 32; o <<= 1) {
        int y = __shfl_up_sync(0xffffffffu, x, o);
        if (lane >= o) x += y;
    }
    if (lane == 31) wsum[wid] = x;
    __syncthreads();
    if (wid == 0) {
        int s = (lane < 8) ? wsum[lane] : 0;
#pragma unroll
        for (int o = 1; o < 8; o <<= 1) {
            int y = __shfl_up_sync(0xffffffffu, s, o);
            if (lane >= o) s += y;
        }
        if (lane < 8) wsum[lane] = s;
    }
    __syncthreads();
    int off = (wid > 0) ? wsum[wid - 1] : 0;
    return x + off;
}

__global__ void scan_block_sum(const int* __restrict__ cnt, int* __restrict__ bsum, int n) {
    __shared__ int wsum[8];
    int i = blockIdx.x * 256 + threadIdx.x;
    int v = (i < n) ? cnt[i] : 0;
    int lane = threadIdx.x & 31, wid = threadIdx.x >> 5;
#pragma unroll
    for (int o = 16; o > 0; o >>= 1) v += __shfl_down_sync(0xffffffffu, v, o);
    if (lane == 0) wsum[wid] = v;
    __syncthreads();
    if (threadIdx.x == 0) {
        int s = 0;
#pragma unroll
        for (int k = 0; k < 8; k++) s += wsum[k];
        bsum[blockIdx.x] = s;
    }
}

__global__ void scan_top(const int* __restrict__ bsum, int* __restrict__ boff, int nb) {
    __shared__ int wsum[8];
    int t = threadIdx.x;
    int v = (t < nb) ? bsum[t] : 0;
    int incl = block_incl_scan(v, wsum);
    if (t < nb) boff[t] = incl - v;
}

__global__ void scan_final(const int* __restrict__ cnt, const int* __restrict__ boff,
                           int* __restrict__ rs, int* __restrict__ rf, int n) {
    __shared__ int wsum[8];
    int i = blockIdx.x * 256 + threadIdx.x;
    int v = (i < n) ? cnt[i] : 0;
    int incl = block_incl_scan(v, wsum);
    int excl = incl - v + boff[blockIdx.x];
    if (i < n) { rs[i] = excl; rf[i] = excl; }
}

__global__ void fill_kernel(const int* __restrict__ src, const int* __restrict__ dst,
                            const float* __restrict__ dinv,
                            int* __restrict__ rf, int* __restrict__ esrc,
                            float* __restrict__ ew, int E) {
    int e = blockIdx.x * blockDim.x + threadIdx.x;
    if (e < E) {
        int s = src[e], d = dst[e];
        int pos = atomicAdd(&rf[d], 1);
        esrc[pos] = s;
        ew[pos] = -dinv[s] * dinv[d];
    }
}

// ---------------- feature assembly (float4, r6 proven) ----------------
__global__ void build_x_kernel(const int* __restrict__ node_attr,
                               const float4* __restrict__ vis,
                               const float4* __restrict__ emb_len,
                               const float4* __restrict__ emb_id,
                               const float4* __restrict__ emb_lng,
                               const float4* __restrict__ emb_lat,
                               float4* __restrict__ x, int n) {
    int idx = blockIdx.x * blockDim.x + threadIdx.x;
    if (idx >= n * 32) return;
    int node = idx >> 5;
    int q = idx & 31;
    float4 v;
    if (q < 16) {
        int which = q >> 2;
        int sub = q & 3;
        int a;
        const float4* tab;
        if (which == 0)      { a = node_attr[node * 4 + 1]; tab = emb_id; }
        else if (which == 1) { a = node_attr[node * 4 + 0]; tab = emb_len; }
        else if (which == 2) { a = node_attr[node * 4 + 2]; tab = emb_lng; }
        else                 { a = node_attr[node * 4 + 3]; tab = emb_lat; }
        v = tab[a * 4 + sub];
    } else {
        v = vis[node * 16 + (q - 16)];
    }
    x[idx] = v;
}

// ---------------- gather propagation (r6 proven, unroll 4) ----------------
__global__ void prop_gather(const float* __restrict__ t,
                            const int* __restrict__ rs, const int* __restrict__ cnt,
                            const int* __restrict__ esrc, const float* __restrict__ ew,
                            float* __restrict__ out, int n) {
    int warp = (blockIdx.x * blockDim.x + threadIdx.x) >> 5;
    int lane = threadIdx.x & 31;
    if (warp >= n) return;
    int start = rs[warp];
    int end = start + cnt[warp];
    float ax = 0.f, ay = 0.f, az = 0.f, aw = 0.f;
    int j = start;
    for (; j + 4 <= end; j += 4) {
        int s0 = esrc[j], s1 = esrc[j + 1], s2 = esrc[j + 2], s3 = esrc[j + 3];
        float w0 = ew[j], w1 = ew[j + 1], w2 = ew[j + 2], w3 = ew[j + 3];
        float4 v0 = *(const float4*)(t + (size_t)s0 * 128 + lane * 4);
        float4 v1 = *(const float4*)(t + (size_t)s1 * 128 + lane * 4);
        float4 v2 = *(const float4*)(t + (size_t)s2 * 128 + lane * 4);
        float4 v3 = *(const float4*)(t + (size_t)s3 * 128 + lane * 4);
        ax += w0 * v0.x; ay += w0 * v0.y; az += w0 * v0.z; aw += w0 * v0.w;
        ax += w1 * v1.x; ay += w1 * v1.y; az += w1 * v1.z; aw += w1 * v1.w;
        ax += w2 * v2.x; ay += w2 * v2.y; az += w2 * v2.z; aw += w2 * v2.w;
        ax += w3 * v3.x; ay += w3 * v3.y; az += w3 * v3.z; aw += w3 * v3.w;
    }
    for (; j < end; j++) {
        int s = esrc[j];
        float w = ew[j];
        float4 v = *(const float4*)(t + (size_t)s * 128 + lane * 4);
        ax += w * v.x; ay += w * v.y; az += w * v.z; aw += w * v.w;
    }
    *(float4*)(out + (size_t)warp * 128 + lane * 4) = make_float4(ax, ay, az, aw);
}

// ---------------- 3xFP16 (Markidis) GEMM, software-pipelined global loads ----------------
__device__ __forceinline__ void split_h(float f, __half& hi, __half& lo) {
    hi = __float2half_rn(f);
    lo = __float2half_rn(f - __half2float(hi));
}

__device__ __forceinline__ void mma_f16(float& d0, float& d1, float& d2, float& d3,
                                        unsigned a0, unsigned a1, unsigned a2, unsigned a3,
                                        unsigned b0, unsigned b1) {
    asm volatile(
        "mma.sync.aligned.m16n8k16.row.col.f32.f16.f16.f32 "
        "{%0,%1,%2,%3}, {%4,%5,%6,%7}, {%8,%9}, {%0,%1,%2,%3};"
        : "+f"(d0), "+f"(d1), "+f"(d2), "+f"(d3)
        : "r"(a0), "r"(a1), "r"(a2), "r"(a3), "r"(b0), "r"(b1));
}

// C[M,NOUT] = A[M,KTOT] @ W[KTOT,NOUT] + bias; EPI: 0=none 1=relu 2=elu
// CHEB: A cols 0..127 = A0, 128..255 = A1, 256..383 = 2*A2 - A0
// Loop schedule: store(regs)->sync->prefetch(next tile)->MMA->sync  (global latency hidden behind MMA)
template<int KTOT, int NOUT, int EPI, bool CHEB>
__global__ void __launch_bounds__(256)
gemm_f16x2(const float* __restrict__ A0, const float* __restrict__ A1,
           const float* __restrict__ A2, const float* __restrict__ W,
           const float* __restrict__ bias, float* __restrict__ C, int M) {
    constexpr int BM = 128, BK = 32, BN = NOUT;
    constexpr int KP = BK / 2;
    constexpr int WARP_N = BN / 2;
    constexpr int NT = WARP_N / 8;
    constexpr int ASTR = BM + 8;
    constexpr int BSTR = BN + 8;
    constexpr int BITERS = (KP * (BN / 4) + 255) / 256;   // 2 for BN=128, 1 for BN=64

    __shared__ __half2 Ah[KP][ASTR], Al[KP][ASTR];
    __shared__ __half2 Bh[KP][BSTR], Bl[KP][BSTR];

    const int tid = threadIdx.x;
    const int w = tid >> 5, lane = tid & 31;
    const int wm = w & 3, wn = w >> 2;
    const int gid = lane >> 2, tig = lane & 3;
    const int row0 = blockIdx.x * BM;

    float acc[2][NT][4];
#pragma unroll
    for (int mt = 0; mt < 2; mt++)
#pragma unroll
        for (int nt = 0; nt < NT; nt++)
#pragma unroll
            for (int q = 0; q < 4; q++) acc[mt][nt][q] = 0.f;

    float4 Ar[4];
    float4 Br[BITERS][2];

    auto loadA = [&](int k0) {
#pragma unroll
        for (int it = 0; it < 4; it++) {
            int i = tid + it * 256;
            int r = i & 127;
            int c4 = i >> 7;
            int grow = row0 + r;
            int gk = k0 + c4 * 4;
            float4 v = make_float4(0.f, 0.f, 0.f, 0.f);
            if (grow < M) {
                if (CHEB) {
                    if (gk < 128) {
                        v = *(const float4*)(A0 + (size_t)grow * 128 + gk);
                    } else if (gk < 256) {
                        v = *(const float4*)(A1 + (size_t)grow * 128 + (gk - 128));
                    } else {
                        float4 p = *(const float4*)(A2 + (size_t)grow * 128 + (gk - 256));
                        float4 t = *(const float4*)(A0 + (size_t)grow * 128 + (gk - 256));
                        v = make_float4(2.f * p.x - t.x, 2.f * p.y - t.y,
                                        2.f * p.z - t.z, 2.f * p.w - t.w);
                    }
                } else {
                    v = *(const float4*)(A0 + (size_t)grow * KTOT + gk);
                }
            }
            Ar[it] = v;
        }
    };

    auto loadB = [&](int k0) {
#pragma unroll
        for (int it = 0; it < BITERS; it++) {
            int i = tid + it * 256;
            int kp = i / (BN / 4);
            int c = (i % (BN / 4)) * 4;
            Br[it][0] = *(const float4*)(W + (size_t)(k0 + 2 * kp + 0) * BN + c);
            Br[it][1] = *(const float4*)(W + (size_t)(k0 + 2 * kp + 1) * BN + c);
        }
    };

    // prologue
    loadA(0);
    loadB(0);

    for (int k0 = 0; k0 < KTOT; k0 += BK) {
        // ---- store staged regs to smem (split) ----
#pragma unroll
        for (int it = 0; it < 4; it++) {
            int i = tid + it * 256;
            int r = i & 127;
            int c4 = i >> 7;
            float4 v = Ar[it];
            __half hx, lx, hy, ly, hz, lz, hw, lw;
            split_h(v.x, hx, lx); split_h(v.y, hy, ly);
            split_h(v.z, hz, lz); split_h(v.w, hw, lw);
            Ah[c4 * 2 + 0][r] = __halves2half2(hx, hy);
            Ah[c4 * 2 + 1][r] = __halves2half2(hz, hw);
            Al[c4 * 2 + 0][r] = __halves2half2(lx, ly);
            Al[c4 * 2 + 1][r] = __halves2half2(lz, lw);
        }
#pragma unroll
        for (int it = 0; it < BITERS; it++) {
            int i = tid + it * 256;
            int kp = i / (BN / 4);
            int c = (i % (BN / 4)) * 4;
            float4 v0 = Br[it][0];
            float4 v1 = Br[it][1];
            float e0[4] = {v0.x, v0.y, v0.z, v0.w};
            float e1[4] = {v1.x, v1.y, v1.z, v1.w};
            __half2 hh[4], ll[4];
#pragma unroll
            for (int jq = 0; jq < 4; jq++) {
                __half h0, l0, h1, l1;
                split_h(e0[jq], h0, l0);
                split_h(e1[jq], h1, l1);
                hh[jq] = __halves2half2(h0, h1);
                ll[jq] = __halves2half2(l0, l1);
            }
            *(uint4*)&Bh[kp][c] = *(const uint4*)hh;
            *(uint4*)&Bl[kp][c] = *(const uint4*)ll;
        }
        __syncthreads();

        // ---- prefetch next tile (latency hidden behind MMAs below) ----
        if (k0 + BK < KTOT) {
            loadA(k0 + BK);
            loadB(k0 + BK);
        }

        // ---- MMA on current smem tile ----
#pragma unroll
        for (int ks = 0; ks < 2; ks++) {
            const int kb = ks * 8 + tig;
            unsigned ah[2][4], al[2][4];
#pragma unroll
            for (int mt = 0; mt < 2; mt++) {
                int m0 = wm * 32 + mt * 16 + gid;
                ah[mt][0] = *(const unsigned*)&Ah[kb][m0];
                ah[mt][1] = *(const unsigned*)&Ah[kb][m0 + 8];
                ah[mt][2] = *(const unsigned*)&Ah[kb + 4][m0];
                ah[mt][3] = *(const unsigned*)&Ah[kb + 4][m0 + 8];
                al[mt][0] = *(const unsigned*)&Al[kb][m0];
                al[mt][1] = *(const unsigned*)&Al[kb][m0 + 8];
                al[mt][2] = *(const unsigned*)&Al[kb + 4][m0];
                al[mt][3] = *(const unsigned*)&Al[kb + 4][m0 + 8];
            }
            unsigned bh[NT][2], bl[NT][2];
#pragma unroll
            for (int nt = 0; nt < NT; nt++) {
                int n0 = wn * WARP_N + nt * 8 + gid;
                bh[nt][0] = *(const unsigned*)&Bh[kb][n0];
                bh[nt][1] = *(const unsigned*)&Bh[kb + 4][n0];
                bl[nt][0] = *(const unsigned*)&Bl[kb][n0];
                bl[nt][1] = *(const unsigned*)&Bl[kb + 4][n0];
            }
#pragma unroll
            for (int mt = 0; mt < 2; mt++)
#pragma unroll
                for (int nt = 0; nt < NT; nt++) {
                    float* d = acc[mt][nt];
                    mma_f16(d[0], d[1], d[2], d[3],
                            ah[mt][0], ah[mt][1], ah[mt][2], ah[mt][3],
                            bh[nt][0], bh[nt][1]);
                    mma_f16(d[0], d[1], d[2], d[3],
                            ah[mt][0], ah[mt][1], ah[mt][2], ah[mt][3],
                            bl[nt][0], bl[nt][1]);
                    mma_f16(d[0], d[1], d[2], d[3],
                            al[mt][0], al[mt][1], al[mt][2], al[mt][3],
                            bh[nt][0], bh[nt][1]);
                }
        }
        __syncthreads();
    }

    // ---- epilogue ----
#pragma unroll
    for (int mt = 0; mt < 2; mt++) {
#pragma unroll
        for (int nt = 0; nt < NT; nt++) {
            int c0 = wn * WARP_N + nt * 8 + tig * 2;
            float bv0 = bias[c0], bv1 = bias[c0 + 1];
#pragma unroll
            for (int half = 0; half < 2; half++) {
                int r = row0 + wm * 32 + mt * 16 + gid + half * 8;
                if (r >= M) continue;
                float v0 = acc[mt][nt][half * 2 + 0] + bv0;
                float v1 = acc[mt][nt][half * 2 + 1] + bv1;
                if (EPI == 1) { v0 = fmaxf(v0, 0.f); v1 = fmaxf(v1, 0.f); }
                else if (EPI == 2) {
                    v0 = (v0 > 0.f) ? v0 : expm1f(v0);
                    v1 = (v1 > 0.f) ? v1 : expm1f(v1);
                }
                *(float2*)(C + (size_t)r * NOUT + c0) = make_float2(v0, v1);
            }
        }
    }
}

// ---------------- launch ----------------
extern "C" void kernel_launch(void* const* d_in, const int* in_sizes, int n_in,
                              void* d_out, int out_size) {
    const int* edge_index = (const int*)d_in[0];
    const int* node_attr = (const int*)d_in[1];
    const float* vis     = (const float*)d_in[2];
    const float* emb_len = (const float*)d_in[3];
    const float* emb_id  = (const float*)d_in[4];
    const float* emb_lng = (const float*)d_in[5];
    const float* emb_lat = (const float*)d_in[6];
    const float* W0  = (const float*)d_in[7];
    const float* b0  = (const float*)d_in[8];
    const float* W1  = (const float*)d_in[9];
    const float* b1  = (const float*)d_in[10];
    const float* P1  = (const float*)d_in[11];
    const float* pb1 = (const float*)d_in[12];
    const float* P2  = (const float*)d_in[13];
    const float* pb2 = (const float*)d_in[14];

    const int E = in_sizes[0] / 2;
    const int N = in_sizes[1] / 4;
    const int* src = edge_index;
    const int* dst = edge_index + E;

    float *x, *t1, *p, *h1, *tmp, *dinv, *ew;
    int *deg, *cnt, *rs, *rf, *bsum, *boff, *esrc;
    cudaGetSymbolAddress((void**)&x,    g_x);
    cudaGetSymbolAddress((void**)&t1,   g_t1);
    cudaGetSymbolAddress((void**)&p,    g_p);
    cudaGetSymbolAddress((void**)&h1,   g_h1);
    cudaGetSymbolAddress((void**)&tmp,  g_tmp);
    cudaGetSymbolAddress((void**)&dinv, g_dinv);
    cudaGetSymbolAddress((void**)&deg,  g_deg);
    cudaGetSymbolAddress((void**)&cnt,  g_cnt);
    cudaGetSymbolAddress((void**)&rs,   g_rs);
    cudaGetSymbolAddress((void**)&rf,   g_rf);
    cudaGetSymbolAddress((void**)&bsum, g_bsum);
    cudaGetSymbolAddress((void**)&boff, g_boff);
    cudaGetSymbolAddress((void**)&esrc, g_esrc);
    cudaGetSymbolAddress((void**)&ew,   g_ew);

    float* hout = (float*)d_out;
    float* zout = hout + (size_t)N * 128;

    const int nb = (N + 255) / 256;
    const int eb = (E + 255) / 256;
    const int gemm_blocks = (N + 127) / 128;
    const int prop_blocks = (N * 32 + 255) / 256;

    // CSR build + dinv (r6 structure)
    cudaMemsetAsync(deg, 0, N * sizeof(int));
    cudaMemsetAsync(cnt, 0, N * sizeof(int));
    count_kernel<<<eb, 256>>>(src, dst, deg, cnt, E);
    dinv_kernel<<<nb, 256>>>(deg, dinv, N);
    scan_block_sum<<<nb, 256>>>(cnt, bsum, N);
    scan_top<<<1, 256>>>(bsum, boff, nb);
    scan_final<<<nb, 256>>>(cnt, boff, rs, rf, N);
    fill_kernel<<<eb, 256>>>(src, dst, dinv, rf, esrc, ew, E);

    // feature assembly
    build_x_kernel<<<(N * 32 + 255) / 256, 256>>>(node_attr, (const float4*)vis,
        (const float4*)emb_len, (const float4*)emb_id,
        (const float4*)emb_lng, (const float4*)emb_lat, (float4*)x, N);

    // ---- conv1 ----
    prop_gather<<<prop_blocks, 256>>>(x, rs, cnt, esrc, ew, t1, N);
    prop_gather<<<prop_blocks, 256>>>(t1, rs, cnt, esrc, ew, p, N);
    gemm_f16x2<384, 128, 1, true><<<gemm_blocks, 256>>>(x, t1, p, W0, b0, h1, N);

    // ---- conv2 ----
    prop_gather<<<prop_blocks, 256>>>(h1, rs, cnt, esrc, ew, t1, N);
    prop_gather<<<prop_blocks, 256>>>(t1, rs, cnt, esrc, ew, p, N);
    gemm_f16x2<384, 128, 1, true><<<gemm_blocks, 256>>>(h1, t1, p, W1, b1, hout, N);

    // ---- projection head ----
    gemm_f16x2<128, 128, 2, false><<<gemm_blocks, 256>>>(hout, nullptr, nullptr, P1, pb1, tmp, N);
    gemm_f16x2<128, 64, 0, false><<<gemm_blocks, 256>>>(tmp, nullptr, nullptr, P2, pb2, zout, N);
}

// round 14
// speedup vs baseline: 1.0986x; 1.0486x over previous
#include <cuda_runtime.h>
#include <cuda_fp16.h>
#include <math.h>

#define NNODES 50000
#define NEDGES 800000

// ---------------- scratch (static device globals; no allocation) ----------------
__device__ __align__(16) float g_x  [NNODES * 128];
__device__ __align__(16) float g_t1 [NNODES * 128];
__device__ __align__(16) float g_p  [NNODES * 128];
__device__ __align__(16) float g_h1 [NNODES * 128];
__device__ int   g_deg [NNODES];
__device__ int   g_cnt [NNODES];
__device__ int   g_rs  [NNODES];
__device__ int   g_rf  [NNODES];
__device__ unsigned long long g_desc[256];   // lookback descriptors (memset per launch)
__device__ int   g_ticket[4];                // block ticket (memset per launch)
__device__ int   g_esrc[NEDGES];
__device__ float g_ew  [NEDGES];

// ---------------- launch #1: feature assembly + degree counting (fused, r9-validated) ----------------
__global__ void buildx_count_kernel(const int* __restrict__ node_attr,
                                    const float4* __restrict__ vis,
                                    const float4* __restrict__ emb_len,
                                    const float4* __restrict__ emb_id,
                                    const float4* __restrict__ emb_lng,
                                    const float4* __restrict__ emb_lat,
                                    float4* __restrict__ x,
                                    const int* __restrict__ src,
                                    const int* __restrict__ dst,
                                    int* __restrict__ deg, int* __restrict__ cnt,
                                    int n, int E) {
    int idx = blockIdx.x * blockDim.x + threadIdx.x;
    if (idx < E) {
        atomicAdd(&deg[src[idx]], 1);
        atomicAdd(&cnt[dst[idx]], 1);
    }
    if (idx >= n * 32) return;
    int node = idx >> 5;
    int q = idx & 31;
    float4 v;
    if (q < 16) {
        int which = q >> 2;
        int sub = q & 3;
        int a;
        const float4* tab;
        if (which == 0)      { a = node_attr[node * 4 + 1]; tab = emb_id; }
        else if (which == 1) { a = node_attr[node * 4 + 0]; tab = emb_len; }
        else if (which == 2) { a = node_attr[node * 4 + 2]; tab = emb_lng; }
        else                 { a = node_attr[node * 4 + 3]; tab = emb_lat; }
        v = tab[a * 4 + sub];
    } else {
        v = vis[node * 16 + (q - 16)];
    }
    x[idx] = v;
}

// ---------------- launch #2: single-pass decoupled-lookback exclusive scan (r9-validated) ----------------
__device__ __forceinline__ int block_incl_scan(int v, int* wsum) {
    int lane = threadIdx.x & 31, wid = threadIdx.x >> 5;
    int x = v;
#pragma unroll
    for (int o = 1; o < 32; o <<= 1) {
        int y = __shfl_up_sync(0xffffffffu, x, o);
        if (lane >= o) x += y;
    }
    if (lane == 31) wsum[wid] = x;
    __syncthreads();
    if (wid == 0) {
        int s = (lane < 8) ? wsum[lane] : 0;
#pragma unroll
        for (int o = 1; o < 8; o <<= 1) {
            int y = __shfl_up_sync(0xffffffffu, s, o);
            if (lane >= o) s += y;
        }
        if (lane < 8) wsum[lane] = s;
    }
    __syncthreads();
    int off = (wid > 0) ? wsum[wid - 1] : 0;
    return x + off;
}

#define FLAG_AGG 1ULL
#define FLAG_PFX 2ULL

__global__ void scan_lookback(const int* __restrict__ cnt,
                              int* __restrict__ rs, int* __restrict__ rf,
                              unsigned long long* __restrict__ desc,
                              int* __restrict__ ticket, int n) {
    __shared__ int wsum[8];
    __shared__ int s_vbid, s_agg, s_prefix;
    if (threadIdx.x == 0) s_vbid = atomicAdd(ticket, 1);
    __syncthreads();
    const int vbid = s_vbid;
    int i = vbid * 256 + threadIdx.x;
    int v = (i < n) ? cnt[i] : 0;
    int incl = block_incl_scan(v, wsum);
    if (threadIdx.x == 255) s_agg = incl;
    __syncthreads();
    int agg = s_agg;
    if (threadIdx.x == 0) {
        if (vbid == 0) {
            atomicExch(&desc[0], (FLAG_PFX << 32) | (unsigned)agg);
            s_prefix = 0;
        } else {
            atomicExch(&desc[vbid], (FLAG_AGG << 32) | (unsigned)agg);
            int running = 0;
            int k = vbid - 1;
            while (true) {
                unsigned long long d = atomicAdd(&desc[k], 0ULL);
                unsigned flag = (unsigned)(d >> 32);
                if (flag == 2u) { running += (int)(unsigned)d; break; }
                if (flag == 1u) { running += (int)(unsigned)d; k--; }
            }
            s_prefix = running;
            atomicExch(&desc[vbid], (FLAG_PFX << 32) | (unsigned)(running + agg));
        }
    }
    __syncthreads();
    int excl = incl - v + s_prefix;
    if (i < n) { rs[i] = excl; rf[i] = excl; }
}

// ---------------- launch #3: fill CSR slots, weight direct from degrees (r9-validated) ----------------
__global__ void fill_kernel(const int* __restrict__ src, const int* __restrict__ dst,
                            const int* __restrict__ deg,
                            int* __restrict__ rf, int* __restrict__ esrc,
                            float* __restrict__ ew, int E) {
    int e = blockIdx.x * blockDim.x + threadIdx.x;
    if (e < E) {
        int s = src[e], d = dst[e];
        int pos = atomicAdd(&rf[d], 1);
        int ds = deg[s], dd = deg[d];
        float w = (dd > 0) ? -rsqrtf((float)ds * (float)dd) : 0.f;
        esrc[pos] = s;
        ew[pos] = w;
    }
}

// ---------------- gather propagation (r6 proven, unroll 4) ----------------
__global__ void prop_gather(const float* __restrict__ t,
                            const int* __restrict__ rs, const int* __restrict__ cnt,
                            const int* __restrict__ esrc, const float* __restrict__ ew,
                            float* __restrict__ out, int n) {
    int warp = (blockIdx.x * blockDim.x + threadIdx.x) >> 5;
    int lane = threadIdx.x & 31;
    if (warp >= n) return;
    int start = rs[warp];
    int end = start + cnt[warp];
    float ax = 0.f, ay = 0.f, az = 0.f, aw = 0.f;
    int j = start;
    for (; j + 4 <= end; j += 4) {
        int s0 = esrc[j], s1 = esrc[j + 1], s2 = esrc[j + 2], s3 = esrc[j + 3];
        float w0 = ew[j], w1 = ew[j + 1], w2 = ew[j + 2], w3 = ew[j + 3];
        float4 v0 = *(const float4*)(t + (size_t)s0 * 128 + lane * 4);
        float4 v1 = *(const float4*)(t + (size_t)s1 * 128 + lane * 4);
        float4 v2 = *(const float4*)(t + (size_t)s2 * 128 + lane * 4);
        float4 v3 = *(const float4*)(t + (size_t)s3 * 128 + lane * 4);
        ax += w0 * v0.x; ay += w0 * v0.y; az += w0 * v0.z; aw += w0 * v0.w;
        ax += w1 * v1.x; ay += w1 * v1.y; az += w1 * v1.z; aw += w1 * v1.w;
        ax += w2 * v2.x; ay += w2 * v2.y; az += w2 * v2.z; aw += w2 * v2.w;
        ax += w3 * v3.x; ay += w3 * v3.y; az += w3 * v3.z; aw += w3 * v3.w;
    }
    for (; j < end; j++) {
        int s = esrc[j];
        float w = ew[j];
        float4 v = *(const float4*)(t + (size_t)s * 128 + lane * 4);
        ax += w * v.x; ay += w * v.y; az += w * v.z; aw += w * v.w;
    }
    *(float4*)(out + (size_t)warp * 128 + lane * 4) = make_float4(ax, ay, az, aw);
}

// ---------------- 3xFP16 (Markidis) helpers ----------------
__device__ __forceinline__ void split_h(float f, __half& hi, __half& lo) {
    hi = __float2half_rn(f);
    lo = __float2half_rn(f - __half2float(hi));
}

__device__ __forceinline__ void mma_f16(float& d0, float& d1, float& d2, float& d3,
                                        unsigned a0, unsigned a1, unsigned a2, unsigned a3,
                                        unsigned b0, unsigned b1) {
    asm volatile(
        "mma.sync.aligned.m16n8k16.row.col.f32.f16.f16.f32 "
        "{%0,%1,%2,%3}, {%4,%5,%6,%7}, {%8,%9}, {%0,%1,%2,%3};"
        : "+f"(d0), "+f"(d1), "+f"(d2), "+f"(d3)
        : "r"(a0), "r"(a1), "r"(a2), "r"(a3), "r"(b0), "r"(b1));
}

// ---------------- conv GEMM (r6 proven, unchanged) ----------------
// C[M,NOUT] = A[M,KTOT] @ W[KTOT,NOUT] + bias; EPI: 0=none 1=relu 2=elu
// CHEB: A cols 0..127 = A0, 128..255 = A1, 256..383 = 2*A2 - A0
template<int KTOT, int NOUT, int EPI, bool CHEB>
__global__ void __launch_bounds__(256)
gemm_f16x2(const float* __restrict__ A0, const float* __restrict__ A1,
           const float* __restrict__ A2, const float* __restrict__ W,
           const float* __restrict__ bias, float* __restrict__ C, int M) {
    constexpr int BM = 128, BK = 32, BN = NOUT;
    constexpr int KP = BK / 2;
    constexpr int WARP_N = BN / 2;
    constexpr int NT = WARP_N / 8;
    constexpr int ASTR = BM + 8;
    constexpr int BSTR = BN + 8;

    __shared__ __half2 Ah[KP][ASTR], Al[KP][ASTR];
    __shared__ __half2 Bh[KP][BSTR], Bl[KP][BSTR];

    const int tid = threadIdx.x;
    const int w = tid >> 5, lane = tid & 31;
    const int wm = w & 3, wn = w >> 2;
    const int gid = lane >> 2, tig = lane & 3;
    const int row0 = blockIdx.x * BM;

    float acc[2][NT][4];
#pragma unroll
    for (int mt = 0; mt < 2; mt++)
#pragma unroll
        for (int nt = 0; nt < NT; nt++)
#pragma unroll
            for (int q = 0; q < 4; q++) acc[mt][nt][q] = 0.f;

    for (int k0 = 0; k0 < KTOT; k0 += BK) {
#pragma unroll
        for (int it = 0; it < 4; it++) {
            int i = tid + it * 256;
            int r = i & 127;
            int c4 = i >> 7;
            int grow = row0 + r;
            int gk = k0 + c4 * 4;
            float4 v = make_float4(0.f, 0.f, 0.f, 0.f);
            if (grow < M) {
                if (CHEB) {
                    if (gk < 128) {
                        v = *(const float4*)(A0 + (size_t)grow * 128 + gk);
                    } else if (gk < 256) {
                        v = *(const float4*)(A1 + (size_t)grow * 128 + (gk - 128));
                    } else {
                        float4 p = *(const float4*)(A2 + (size_t)grow * 128 + (gk - 256));
                        float4 t = *(const float4*)(A0 + (size_t)grow * 128 + (gk - 256));
                        v = make_float4(2.f * p.x - t.x, 2.f * p.y - t.y,
                                        2.f * p.z - t.z, 2.f * p.w - t.w);
                    }
                } else {
                    v = *(const float4*)(A0 + (size_t)grow * KTOT + gk);
                }
            }
            __half hx, lx, hy, ly, hz, lz, hw, lw;
            split_h(v.x, hx, lx); split_h(v.y, hy, ly);
            split_h(v.z, hz, lz); split_h(v.w, hw, lw);
            Ah[c4 * 2 + 0][r] = __halves2half2(hx, hy);
            Ah[c4 * 2 + 1][r] = __halves2half2(hz, hw);
            Al[c4 * 2 + 0][r] = __halves2half2(lx, ly);
            Al[c4 * 2 + 1][r] = __halves2half2(lz, lw);
        }
        constexpr int BSLOTS = KP * (BN / 4);
#pragma unroll
        for (int it = 0; it < (BSLOTS + 255) / 256; it++) {
            int i = tid + it * 256;
            if (BSLOTS % 256 != 0 && i >= BSLOTS) break;
            int kp = i / (BN / 4);
            int c = (i % (BN / 4)) * 4;
            float4 v0 = *(const float4*)(W + (size_t)(k0 + 2 * kp + 0) * BN + c);
            float4 v1 = *(const float4*)(W + (size_t)(k0 + 2 * kp + 1) * BN + c);
            float e0[4] = {v0.x, v0.y, v0.z, v0.w};
            float e1[4] = {v1.x, v1.y, v1.z, v1.w};
            __half2 hh[4], ll[4];
#pragma unroll
            for (int jq = 0; jq < 4; jq++) {
                __half h0, l0, h1, l1;
                split_h(e0[jq], h0, l0);
                split_h(e1[jq], h1, l1);
                hh[jq] = __halves2half2(h0, h1);
                ll[jq] = __halves2half2(l0, l1);
            }
            *(uint4*)&Bh[kp][c] = *(const uint4*)hh;
            *(uint4*)&Bl[kp][c] = *(const uint4*)ll;
        }
        __syncthreads();

#pragma unroll
        for (int ks = 0; ks < 2; ks++) {
            const int kb = ks * 8 + tig;
            unsigned ah[2][4], al[2][4];
#pragma unroll
            for (int mt = 0; mt < 2; mt++) {
                int m0 = wm * 32 + mt * 16 + gid;
                ah[mt][0] = *(const unsigned*)&Ah[kb][m0];
                ah[mt][1] = *(const unsigned*)&Ah[kb][m0 + 8];
                ah[mt][2] = *(const unsigned*)&Ah[kb + 4][m0];
                ah[mt][3] = *(const unsigned*)&Ah[kb + 4][m0 + 8];
                al[mt][0] = *(const unsigned*)&Al[kb][m0];
                al[mt][1] = *(const unsigned*)&Al[kb][m0 + 8];
                al[mt][2] = *(const unsigned*)&Al[kb + 4][m0];
                al[mt][3] = *(const unsigned*)&Al[kb + 4][m0 + 8];
            }
            unsigned bh[NT][2], bl[NT][2];
#pragma unroll
            for (int nt = 0; nt < NT; nt++) {
                int n0 = wn * WARP_N + nt * 8 + gid;
                bh[nt][0] = *(const unsigned*)&Bh[kb][n0];
                bh[nt][1] = *(const unsigned*)&Bh[kb + 4][n0];
                bl[nt][0] = *(const unsigned*)&Bl[kb][n0];
                bl[nt][1] = *(const unsigned*)&Bl[kb + 4][n0];
            }
#pragma unroll
            for (int mt = 0; mt < 2; mt++)
#pragma unroll
                for (int nt = 0; nt < NT; nt++) {
                    float* d = acc[mt][nt];
                    mma_f16(d[0], d[1], d[2], d[3],
                            ah[mt][0], ah[mt][1], ah[mt][2], ah[mt][3],
                            bh[nt][0], bh[nt][1]);
                    mma_f16(d[0], d[1], d[2], d[3],
                            ah[mt][0], ah[mt][1], ah[mt][2], ah[mt][3],
                            bl[nt][0], bl[nt][1]);
                    mma_f16(d[0], d[1], d[2], d[3],
                            al[mt][0], al[mt][1], al[mt][2], al[mt][3],
                            bh[nt][0], bh[nt][1]);
                }
        }
        __syncthreads();
    }

#pragma unroll
    for (int mt = 0; mt < 2; mt++) {
#pragma unroll
        for (int nt = 0; nt < NT; nt++) {
            int c0 = wn * WARP_N + nt * 8 + tig * 2;
            float bv0 = bias[c0], bv1 = bias[c0 + 1];
#pragma unroll
            for (int half = 0; half < 2; half++) {
                int r = row0 + wm * 32 + mt * 16 + gid + half * 8;
                if (r >= M) continue;
                float v0 = acc[mt][nt][half * 2 + 0] + bv0;
                float v1 = acc[mt][nt][half * 2 + 1] + bv1;
                if (EPI == 1) { v0 = fmaxf(v0, 0.f); v1 = fmaxf(v1, 0.f); }
                else if (EPI == 2) {
                    v0 = (v0 > 0.f) ? v0 : expm1f(v0);
                    v1 = (v1 > 0.f) ? v1 : expm1f(v1);
                }
                *(float2*)(C + (size_t)r * NOUT + c0) = make_float2(v0, v1);
            }
        }
    }
}

// ---------------- fused projection head: z = elu(h@P1+pb1)@P2+pb2 ----------------
// Stage 1 keeps z1[128][128] in registers (256 thr x 64 acc); stage 2 spills
// per-32k chunks into re-aliased smem as split fp16 and MMAs against P2.
__global__ void __launch_bounds__(256)
head_fused(const float* __restrict__ H, const float* __restrict__ P1,
           const float* __restrict__ pb1, const float* __restrict__ P2,
           const float* __restrict__ pb2, float* __restrict__ Z, int M) {
    constexpr int STR = 136;          // half2 stride (conflict-free: 136 mod 32 words = 8)
    constexpr int SLAB = 16 * STR;
    __shared__ __half2 sb[4 * SLAB];
    __half2* Ah = sb;
    __half2* Al = sb + SLAB;
    __half2* Bh = sb + 2 * SLAB;
    __half2* Bl = sb + 3 * SLAB;

    const int tid = threadIdx.x;
    const int w = tid >> 5, lane = tid & 31;
    const int wm = w & 3, wn = w >> 2;        // wn in {0,1}
    const int gid = lane >> 2, tig = lane & 3;
    const int row0 = blockIdx.x * 128;

    // ======== stage 1: z1 = elu(H @ P1 + pb1), NT=8, WARP_N=64 ========
    float acc[2][8][4];
#pragma unroll
    for (int mt = 0; mt < 2; mt++)
#pragma unroll
        for (int nt = 0; nt < 8; nt++)
#pragma unroll
            for (int q = 0; q < 4; q++) acc[mt][nt][q] = 0.f;

    for (int k0 = 0; k0 < 128; k0 += 32) {
        // A tile from H
#pragma unroll
        for (int it = 0; it < 4; it++) {
            int i = tid + it * 256;
            int r = i & 127;
            int c4 = i >> 7;
            int grow = row0 + r;
            int gk = k0 + c4 * 4;
            float4 v = make_float4(0.f, 0.f, 0.f, 0.f);
            if (grow < M) v = *(const float4*)(H + (size_t)grow * 128 + gk);
            __half hx, lx, hy, ly, hz, lz, hw, lw;
            split_h(v.x, hx, lx); split_h(v.y, hy, ly);
            split_h(v.z, hz, lz); split_h(v.w, hw, lw);
            Ah[(c4 * 2 + 0) * STR + r] = __halves2half2(hx, hy);
            Ah[(c4 * 2 + 1) * STR + r] = __halves2half2(hz, hw);
            Al[(c4 * 2 + 0) * STR + r] = __halves2half2(lx, ly);
            Al[(c4 * 2 + 1) * STR + r] = __halves2half2(lz, lw);
        }
        // B tile from P1 (BN=128): 512 slots, 2 iters
#pragma unroll
        for (int it = 0; it < 2; it++) {
            int i = tid + it * 256;
            int kp = i >> 5;
            int c = (i & 31) * 4;
            float4 v0 = *(const float4*)(P1 + (size_t)(k0 + 2 * kp + 0) * 128 + c);
            float4 v1 = *(const float4*)(P1 + (size_t)(k0 + 2 * kp + 1) * 128 + c);
            float e0[4] = {v0.x, v0.y, v0.z, v0.w};
            float e1[4] = {v1.x, v1.y, v1.z, v1.w};
            __half2 hh[4], ll[4];
#pragma unroll
            for (int jq = 0; jq < 4; jq++) {
                __half h0, l0, h1, l1;
                split_h(e0[jq], h0, l0);
                split_h(e1[jq], h1, l1);
                hh[jq] = __halves2half2(h0, h1);
                ll[jq] = __halves2half2(l0, l1);
            }
            *(uint4*)&Bh[kp * STR + c] = *(const uint4*)hh;
            *(uint4*)&Bl[kp * STR + c] = *(const uint4*)ll;
        }
        __syncthreads();

#pragma unroll
        for (int ks = 0; ks < 2; ks++) {
            const int kb = ks * 8 + tig;
            unsigned ah[2][4], al[2][4];
#pragma unroll
            for (int mt = 0; mt < 2; mt++) {
                int m0 = wm * 32 + mt * 16 + gid;
                ah[mt][0] = *(const unsigned*)&Ah[kb * STR + m0];
                ah[mt][1] = *(const unsigned*)&Ah[kb * STR + m0 + 8];
                ah[mt][2] = *(const unsigned*)&Ah[(kb + 4) * STR + m0];
                ah[mt][3] = *(const unsigned*)&Ah[(kb + 4) * STR + m0 + 8];
                al[mt][0] = *(const unsigned*)&Al[kb * STR + m0];
                al[mt][1] = *(const unsigned*)&Al[kb * STR + m0 + 8];
                al[mt][2] = *(const unsigned*)&Al[(kb + 4) * STR + m0];
                al[mt][3] = *(const unsigned*)&Al[(kb + 4) * STR + m0 + 8];
            }
            unsigned bh[8][2], bl[8][2];
#pragma unroll
            for (int nt = 0; nt < 8; nt++) {
                int n0 = wn * 64 + nt * 8 + gid;
                bh[nt][0] = *(const unsigned*)&Bh[kb * STR + n0];
                bh[nt][1] = *(const unsigned*)&Bh[(kb + 4) * STR + n0];
                bl[nt][0] = *(const unsigned*)&Bl[kb * STR + n0];
                bl[nt][1] = *(const unsigned*)&Bl[(kb + 4) * STR + n0];
            }
#pragma unroll
            for (int mt = 0; mt < 2; mt++)
#pragma unroll
                for (int nt = 0; nt < 8; nt++) {
                    float* d = acc[mt][nt];
                    mma_f16(d[0], d[1], d[2], d[3],
                            ah[mt][0], ah[mt][1], ah[mt][2], ah[mt][3],
                            bh[nt][0], bh[nt][1]);
                    mma_f16(d[0], d[1], d[2], d[3],
                            ah[mt][0], ah[mt][1], ah[mt][2], ah[mt][3],
                            bl[nt][0], bl[nt][1]);
                    mma_f16(d[0], d[1], d[2], d[3],
                            al[mt][0], al[mt][1], al[mt][2], al[mt][3],
                            bh[nt][0], bh[nt][1]);
                }
        }
        __syncthreads();
    }

    // bias + elu into acc (z1 stays in registers)
#pragma unroll
    for (int mt = 0; mt < 2; mt++)
#pragma unroll
        for (int nt = 0; nt < 8; nt++) {
            int c0 = wn * 64 + nt * 8 + tig * 2;
            float bv0 = pb1[c0], bv1 = pb1[c0 + 1];
#pragma unroll
            for (int half = 0; half < 2; half++) {
                float v0 = acc[mt][nt][half * 2 + 0] + bv0;
                float v1 = acc[mt][nt][half * 2 + 1] + bv1;
                acc[mt][nt][half * 2 + 0] = (v0 > 0.f) ? v0 : expm1f(v0);
                acc[mt][nt][half * 2 + 1] = (v1 > 0.f) ? v1 : expm1f(v1);
            }
        }

    // ======== stage 2: z2 = z1 @ P2 + pb2, NT2=4, WARP_N2=32 ========
    float acc2[2][4][4];
#pragma unroll
    for (int mt = 0; mt < 2; mt++)
#pragma unroll
        for (int nt = 0; nt < 4; nt++)
#pragma unroll
            for (int q = 0; q < 4; q++) acc2[mt][nt][q] = 0.f;

    for (int kc = 0; kc < 4; kc++) {
        __syncthreads();   // protect smem reuse
        // owning warps (wn == kc>>1) spill z1 chunk cols [kc*32, kc*32+32)
        if (wn == (kc >> 1)) {
            int ntbase = (kc & 1) * 4;
#pragma unroll
            for (int mt = 0; mt < 2; mt++)
#pragma unroll
                for (int ntl = 0; ntl < 4; ntl++) {
                    int nt = ntbase + ntl;
                    int kp = ntl * 4 + tig;
#pragma unroll
                    for (int half = 0; half < 2; half++) {
                        int row = wm * 32 + mt * 16 + gid + half * 8;
                        float v0 = acc[mt][nt][half * 2 + 0];
                        float v1 = acc[mt][nt][half * 2 + 1];
                        __half h0, l0, h1, l1;
                        split_h(v0, h0, l0);
                        split_h(v1, h1, l1);
                        Ah[kp * STR + row] = __halves2half2(h0, h1);
                        Al[kp * STR + row] = __halves2half2(l0, l1);
                    }
                }
        }
        // stage B2 from P2 chunk: 16 kp x 16 col-groups = 256 slots
        {
            int kp = tid >> 4;
            int c = (tid & 15) * 4;
            float4 v0 = *(const float4*)(P2 + (size_t)(kc * 32 + 2 * kp + 0) * 64 + c);
            float4 v1 = *(const float4*)(P2 + (size_t)(kc * 32 + 2 * kp + 1) * 64 + c);
            float e0[4] = {v0.x, v0.y, v0.z, v0.w};
            float e1[4] = {v1.x, v1.y, v1.z, v1.w};
            __half2 hh[4], ll[4];
#pragma unroll
            for (int jq = 0; jq < 4; jq++) {
                __half h0, l0, h1, l1;
                split_h(e0[jq], h0, l0);
                split_h(e1[jq], h1, l1);
                hh[jq] = __halves2half2(h0, h1);
                ll[jq] = __halves2half2(l0, l1);
            }
            *(uint4*)&Bh[kp * STR + c] = *(const uint4*)hh;
            *(uint4*)&Bl[kp * STR + c] = *(const uint4*)ll;
        }
        __syncthreads();

#pragma unroll
        for (int ks = 0; ks < 2; ks++) {
            const int kb = ks * 8 + tig;
            unsigned ah[2][4], al[2][4];
#pragma unroll
            for (int mt = 0; mt < 2; mt++) {
                int m0 = wm * 32 + mt * 16 + gid;
                ah[mt][0] = *(const unsigned*)&Ah[kb * STR + m0];
                ah[mt][1] = *(const unsigned*)&Ah[kb * STR + m0 + 8];
                ah[mt][2] = *(const unsigned*)&Ah[(kb + 4) * STR + m0];
                ah[mt][3] = *(const unsigned*)&Ah[(kb + 4) * STR + m0 + 8];
                al[mt][0] = *(const unsigned*)&Al[kb * STR + m0];
                al[mt][1] = *(const unsigned*)&Al[kb * STR + m0 + 8];
                al[mt][2] = *(const unsigned*)&Al[(kb + 4) * STR + m0];
                al[mt][3] = *(const unsigned*)&Al[(kb + 4) * STR + m0 + 8];
            }
            unsigned bh[4][2], bl[4][2];
#pragma unroll
            for (int nt = 0; nt < 4; nt++) {
                int n0 = wn * 32 + nt * 8 + gid;
                bh[nt][0] = *(const unsigned*)&Bh[kb * STR + n0];
                bh[nt][1] = *(const unsigned*)&Bh[(kb + 4) * STR + n0];
                bl[nt][0] = *(const unsigned*)&Bl[kb * STR + n0];
                bl[nt][1] = *(const unsigned*)&Bl[(kb + 4) * STR + n0];
            }
#pragma unroll
            for (int mt = 0; mt < 2; mt++)
#pragma unroll
                for (int nt = 0; nt < 4; nt++) {
                    float* d = acc2[mt][nt];
                    mma_f16(d[0], d[1], d[2], d[3],
                            ah[mt][0], ah[mt][1], ah[mt][2], ah[mt][3],
                            bh[nt][0], bh[nt][1]);
                    mma_f16(d[0], d[1], d[2], d[3],
                            ah[mt][0], ah[mt][1], ah[mt][2], ah[mt][3],
                            bl[nt][0], bl[nt][1]);
                    mma_f16(d[0], d[1], d[2], d[3],
                            al[mt][0], al[mt][1], al[mt][2], al[mt][3],
                            bh[nt][0], bh[nt][1]);
                }
        }
    }

    // epilogue: z2 + pb2
#pragma unroll
    for (int mt = 0; mt < 2; mt++)
#pragma unroll
        for (int nt = 0; nt < 4; nt++) {
            int c0 = wn * 32 + nt * 8 + tig * 2;
            float bv0 = pb2[c0], bv1 = pb2[c0 + 1];
#pragma unroll
            for (int half = 0; half < 2; half++) {
                int r = row0 + wm * 32 + mt * 16 + gid + half * 8;
                if (r >= M) continue;
                float v0 = acc2[mt][nt][half * 2 + 0] + bv0;
                float v1 = acc2[mt][nt][half * 2 + 1] + bv1;
                *(float2*)(Z + (size_t)r * 64 + c0) = make_float2(v0, v1);
            }
        }
}

// ---------------- launch ----------------
extern "C" void kernel_launch(void* const* d_in, const int* in_sizes, int n_in,
                              void* d_out, int out_size) {
    const int* edge_index = (const int*)d_in[0];
    const int* node_attr = (const int*)d_in[1];
    const float* vis     = (const float*)d_in[2];
    const float* emb_len = (const float*)d_in[3];
    const float* emb_id  = (const float*)d_in[4];
    const float* emb_lng = (const float*)d_in[5];
    const float* emb_lat = (const float*)d_in[6];
    const float* W0  = (const float*)d_in[7];
    const float* b0  = (const float*)d_in[8];
    const float* W1  = (const float*)d_in[9];
    const float* b1  = (const float*)d_in[10];
    const float* P1  = (const float*)d_in[11];
    const float* pb1 = (const float*)d_in[12];
    const float* P2  = (const float*)d_in[13];
    const float* pb2 = (const float*)d_in[14];

    const int E = in_sizes[0] / 2;
    const int N = in_sizes[1] / 4;
    const int* src = edge_index;
    const int* dst = edge_index + E;

    float *x, *t1, *p, *h1, *ew;
    int *deg, *cnt, *rs, *rf, *esrc, *ticket;
    unsigned long long* desc;
    cudaGetSymbolAddress((void**)&x,    g_x);
    cudaGetSymbolAddress((void**)&t1,   g_t1);
    cudaGetSymbolAddress((void**)&p,    g_p);
    cudaGetSymbolAddress((void**)&h1,   g_h1);
    cudaGetSymbolAddress((void**)&deg,  g_deg);
    cudaGetSymbolAddress((void**)&cnt,  g_cnt);
    cudaGetSymbolAddress((void**)&rs,   g_rs);
    cudaGetSymbolAddress((void**)&rf,   g_rf);
    cudaGetSymbolAddress((void**)&desc, g_desc);
    cudaGetSymbolAddress((void**)&ticket, g_ticket);
    cudaGetSymbolAddress((void**)&esrc, g_esrc);
    cudaGetSymbolAddress((void**)&ew,   g_ew);

    float* hout = (float*)d_out;
    float* zout = hout + (size_t)N * 128;

    const int nb = (N + 255) / 256;
    const int eb = (E + 255) / 256;
    const int gemm_blocks = (N + 127) / 128;
    const int prop_blocks = (N * 32 + 255) / 256;
    const int bx_blocks = (N * 32 + 255) / 256;

    // resets (async memsets — not kernel launches)
    cudaMemsetAsync(deg, 0, N * sizeof(int));
    cudaMemsetAsync(cnt, 0, N * sizeof(int));
    cudaMemsetAsync(desc, 0, 256 * sizeof(unsigned long long));
    cudaMemsetAsync(ticket, 0, 4 * sizeof(int));

    // setup: 3 kernels (prop #1 is kernel launch 4 — profiled)
    buildx_count_kernel<<<bx_blocks, 256>>>(node_attr, (const float4*)vis,
        (const float4*)emb_len, (const float4*)emb_id,
        (const float4*)emb_lng, (const float4*)emb_lat, (float4*)x,
        src, dst, deg, cnt, N, E);
    scan_lookback<<<nb, 256>>>(cnt, rs, rf, desc, ticket, N);
    fill_kernel<<<eb, 256>>>(src, dst, deg, rf, esrc, ew, E);

    // ---- conv1 ----
    prop_gather<<<prop_blocks, 256>>>(x, rs, cnt, esrc, ew, t1, N);
    prop_gather<<<prop_blocks, 256>>>(t1, rs, cnt, esrc, ew, p, N);
    gemm_f16x2<384, 128, 1, true><<<gemm_blocks, 256>>>(x, t1, p, W0, b0, h1, N);

    // ---- conv2 ----
    prop_gather<<<prop_blocks, 256>>>(h1, rs, cnt, esrc, ew, t1, N);
    prop_gather<<<prop_blocks, 256>>>(t1, rs, cnt, esrc, ew, p, N);
    gemm_f16x2<384, 128, 1, true><<<gemm_blocks, 256>>>(h1, t1, p, W1, b1, hout, N);

    // ---- fused projection head ----
    head_fused<<<gemm_blocks, 256>>>(hout, P1, pb1, P2, pb2, zout, N);
}